// round 2
// baseline (speedup 1.0000x reference)
#include <cuda_runtime.h>
#include <math.h>

#define B_     16
#define CH_    22
#define T_     1001
#define F_     36
#define KT_    65
#define T1_    937            // T - KT + 1
#define GC_    (F_*CH_)       // 792
#define KC_    15
#define U_     885            // D/E length
#define SLEN_  935            // S length
#define Q_     43
#define NCROPS_ 501
#define OUT_   4
#define FLAT_  (F_*Q_)        // 1548
#define EPSF   1e-5f

// ---------------- scratch (device globals; no allocation) ----------------
__device__ float d_h1[(size_t)B_*GC_*T1_];   // temporal act, layout [b][g*CH+ch][t]
__device__ float d_h2[(size_t)B_*F_*T1_];    // spatial act [b][f][t]
__device__ float d_S [(size_t)B_*F_*SLEN_];  // 3-mean      [b][f][t]
__device__ float d_E [(size_t)B_*F_*U_];     // elu(bn(D))  [b][f][u]
__device__ float d_G [(size_t)B_*FLAT_];     // summed pool2 [b][f*43+q]
__device__ float d_scale_t[F_], d_shift_t[F_];
__device__ float d_scale_s[F_], d_shift_s[F_];
__device__ float d_scale_c[F_], d_shift_c[F_];

__device__ __forceinline__ float eluf(float x) {
    return x > 0.0f ? x : expm1f(x);
}

// ---------------- prep: fold bias + BN ----------------
__global__ void prep_kernel(
    const float* __restrict__ b_t, const float* __restrict__ g_t, const float* __restrict__ bb_t,
    const float* __restrict__ m_t, const float* __restrict__ v_t,
    const float* __restrict__ b_s, const float* __restrict__ g_s, const float* __restrict__ bb_s,
    const float* __restrict__ m_s, const float* __restrict__ v_s,
    const float* __restrict__ b_c, const float* __restrict__ g_c, const float* __restrict__ bb_c,
    const float* __restrict__ m_c, const float* __restrict__ v_c)
{
    int i = threadIdx.x;
    if (i < F_) {
        float inv;
        inv = g_t[i] / sqrtf(v_t[i] + EPSF);
        d_scale_t[i] = inv; d_shift_t[i] = (b_t[i] - m_t[i]) * inv + bb_t[i];
        inv = g_s[i] / sqrtf(v_s[i] + EPSF);
        d_scale_s[i] = inv; d_shift_s[i] = (b_s[i] - m_s[i]) * inv + bb_s[i];
        inv = g_c[i] / sqrtf(v_c[i] + EPSF);
        d_scale_c[i] = inv; d_shift_c[i] = (b_c[i] - m_c[i]) * inv + bb_c[i];
    }
}

// ---------------- K1: temporal conv + BN + ELU ----------------
// grid (ceil(T1/256), CH, B), block 128. Each thread computes 2 t positions x 36 filters.
__global__ void __launch_bounds__(128) k1_temporal(
    const float* __restrict__ x, const float* __restrict__ w_t)
{
    __shared__ float sx[256 + KT_ - 1];      // 320
    __shared__ float sw[F_ * KT_];           // 2340
    const int b  = blockIdx.z;
    const int ch = blockIdx.y;
    const int t0 = blockIdx.x * 256;
    const int tid = threadIdx.x;
    const float* xp = x + ((size_t)b * CH_ + ch) * T_;

    for (int i = tid; i < F_ * KT_; i += 128) sw[i] = w_t[i];
    const int nload = min(256 + KT_ - 1, T_ - t0);
    for (int i = tid; i < 256 + KT_ - 1; i += 128)
        sx[i] = (i < nload) ? xp[t0 + i] : 0.0f;
    __syncthreads();

    float acc0[F_], acc1[F_];
#pragma unroll
    for (int g = 0; g < F_; g++) { acc0[g] = 0.0f; acc1[g] = 0.0f; }

#pragma unroll 1
    for (int k = 0; k < KT_; k++) {
        float x0 = sx[tid + k];
        float x1 = sx[tid + 128 + k];
#pragma unroll
        for (int g = 0; g < F_; g++) {
            float w = sw[g * KT_ + k];
            acc0[g] = fmaf(w, x0, acc0[g]);
            acc1[g] = fmaf(w, x1, acc1[g]);
        }
    }

    const int ta = t0 + tid;
    const int tb = ta + 128;
#pragma unroll
    for (int g = 0; g < F_; g++) {
        float sc = d_scale_t[g], sh = d_shift_t[g];
        size_t base = ((size_t)b * GC_ + (size_t)g * CH_ + ch) * T1_;
        if (ta < T1_) d_h1[base + ta] = eluf(fmaf(acc0[g], sc, sh));
        if (tb < T1_) d_h1[base + tb] = eluf(fmaf(acc1[g], sc, sh));
    }
}

// ---------------- K2: spatial conv (36x792 GEMM per b) + BN + ELU ----------------
// grid (ceil(T1/128), B), block 128. 1 t/thread, 36 accumulators, K-chunks of 8.
__global__ void __launch_bounds__(128) k2_spatial(const float* __restrict__ w_s)
{
    __shared__ float sh_[8][128];
    __shared__ float sw[8][F_];
    const int b  = blockIdx.y;
    const int t0 = blockIdx.x * 128;
    const int tid = threadIdx.x;
    const int t  = t0 + tid;

    float acc[F_];
#pragma unroll
    for (int f = 0; f < F_; f++) acc[f] = 0.0f;

#pragma unroll 1
    for (int kk0 = 0; kk0 < GC_; kk0 += 8) {
        __syncthreads();
        // load 8 rows of h1 (coalesced) and 8x36 weights
        for (int i = tid; i < 8 * 128; i += 128) {
            int kk = i >> 7, tt = i & 127;
            int tg = t0 + tt;
            sh_[kk][tt] = (tg < T1_) ? d_h1[((size_t)b * GC_ + kk0 + kk) * T1_ + tg] : 0.0f;
        }
        for (int i = tid; i < 8 * F_; i += 128) {
            int f = i >> 3, kk = i & 7;
            sw[kk][f] = w_s[(size_t)f * GC_ + kk0 + kk];
        }
        __syncthreads();
#pragma unroll
        for (int kk = 0; kk < 8; kk++) {
            float h = sh_[kk][tid];
#pragma unroll
            for (int f = 0; f < F_; f++)
                acc[f] = fmaf(sw[kk][f], h, acc[f]);
        }
    }

    if (t < T1_) {
#pragma unroll
        for (int f = 0; f < F_; f++) {
            float v = fmaf(acc[f], d_scale_s[f], d_shift_s[f]);
            d_h2[((size_t)b * F_ + f) * T1_ + t] = eluf(v);
        }
    }
}

// ---------------- K2b: sliding 3-mean S ----------------
__global__ void k2b_pool(void)
{
    int i = blockIdx.x * blockDim.x + threadIdx.x;
    const int n = B_ * F_ * SLEN_;
    if (i < n) {
        int t  = i % SLEN_;
        int bf = i / SLEN_;
        const float* h = d_h2 + (size_t)bf * T1_;
        d_S[i] = (h[t] + h[t + 1] + h[t + 2]) * (1.0f / 3.0f);
    }
}

// ---------------- K3: dilation-3 conv (36 x (36*15)) + BN + ELU -> E ----------------
// grid (ceil(U/128), B), block 128. 1 u/thread, 36 accumulators.
__global__ void __launch_bounds__(128) k3_dconv(const float* __restrict__ w_c)
{
    __shared__ float sS[F_][128 + 3 * (KC_ - 1)];  // 36 x 170
    __shared__ float sw[KC_ * F_];                 // 540, layout [j][f]
    const int b  = blockIdx.y;
    const int u0 = blockIdx.x * 128;
    const int tid = threadIdx.x;

    // load S tile (all 36 channels)
    for (int i = tid; i < F_ * 170; i += 128) {
        int g = i / 170, uu = i % 170;
        int ug = u0 + uu;
        sS[g][uu] = (ug < SLEN_) ? d_S[((size_t)b * F_ + g) * SLEN_ + ug] : 0.0f;
    }

    float acc[F_];
#pragma unroll
    for (int f = 0; f < F_; f++) acc[f] = 0.0f;

#pragma unroll 1
    for (int g = 0; g < F_; g++) {
        __syncthreads();  // protect sw from previous iteration (and S load on first)
        for (int i = tid; i < KC_ * F_; i += 128) {
            int f = i % F_, j = i / F_;
            sw[i] = w_c[(size_t)f * (F_ * KC_) + g * KC_ + j];
        }
        __syncthreads();
#pragma unroll
        for (int j = 0; j < KC_; j++) {
            float s = sS[g][tid + 3 * j];
#pragma unroll
            for (int f = 0; f < F_; f++)
                acc[f] = fmaf(sw[j * F_ + f], s, acc[f]);
        }
    }

    const int u = u0 + tid;
    if (u < U_) {
#pragma unroll
        for (int f = 0; f < F_; f++) {
            float v = fmaf(acc[f], d_scale_c[f], d_shift_c[f]);
            d_E[((size_t)b * F_ + f) * U_ + u] = eluf(v);
        }
    }
}

// ---------------- K4: per-(b,f) prefix scan + windowed sums -> G ----------------
// grid (F, B), block 1024.
__global__ void __launch_bounds__(1024) k4_windows(void)
{
    __shared__ float buf0[1024];
    __shared__ float buf1[1024];
    const int b = blockIdx.y, f = blockIdx.x;
    const int tid = threadIdx.x;
    const float* Ep = d_E + ((size_t)b * F_ + f) * U_;

    buf0[tid] = (tid < U_) ? Ep[tid] : 0.0f;
    __syncthreads();

    float* src = buf0;
    float* dst = buf1;
#pragma unroll
    for (int off = 1; off < 1024; off <<= 1) {
        dst[tid] = src[tid] + ((tid >= off) ? src[tid - off] : 0.0f);
        __syncthreads();
        float* tmp = src; src = dst; dst = tmp;
    }
    // src = inclusive prefix sum of E

    if (tid < Q_) {
        int q = tid;
        float s = 0.0f;
#pragma unroll
        for (int c = 0; c <= 6; c += 3) {
            int a = 9 * q + c;
            float lo = (a > 0) ? src[a - 1] : 0.0f;
            s += src[a + 500] - lo;
        }
        d_G[(size_t)b * FLAT_ + f * Q_ + q] = s * (1.0f / 3.0f);
    }
}

// ---------------- K5: FC reduce ----------------
// grid B, block 128.
__global__ void __launch_bounds__(128) k5_fc(
    const float* __restrict__ w_fc, const float* __restrict__ b_fc,
    float* __restrict__ out)
{
    __shared__ float red[OUT_][128];
    const int b = blockIdx.x;
    const int tid = threadIdx.x;

    float p[OUT_];
#pragma unroll
    for (int o = 0; o < OUT_; o++) p[o] = 0.0f;

    for (int i = tid; i < FLAT_; i += 128) {
        float g = d_G[(size_t)b * FLAT_ + i];
#pragma unroll
        for (int o = 0; o < OUT_; o++)
            p[o] = fmaf(g, w_fc[(size_t)o * FLAT_ + i], p[o]);
    }
#pragma unroll
    for (int o = 0; o < OUT_; o++) red[o][tid] = p[o];
    __syncthreads();
    for (int s = 64; s > 0; s >>= 1) {
        if (tid < s) {
#pragma unroll
            for (int o = 0; o < OUT_; o++) red[o][tid] += red[o][tid + s];
        }
        __syncthreads();
    }
    if (tid < OUT_)
        out[b * OUT_ + tid] = red[tid][0] * (1.0f / NCROPS_) + b_fc[tid];
}

// ---------------- launch ----------------
extern "C" void kernel_launch(void* const* d_in, const int* in_sizes, int n_in,
                              void* d_out, int out_size)
{
    const float* x      = (const float*)d_in[0];
    const float* w_t    = (const float*)d_in[1];
    const float* b_t    = (const float*)d_in[2];
    const float* bn_t_g = (const float*)d_in[3];
    const float* bn_t_b = (const float*)d_in[4];
    const float* bn_t_m = (const float*)d_in[5];
    const float* bn_t_v = (const float*)d_in[6];
    const float* w_s    = (const float*)d_in[7];
    const float* b_s    = (const float*)d_in[8];
    const float* bn_s_g = (const float*)d_in[9];
    const float* bn_s_b = (const float*)d_in[10];
    const float* bn_s_m = (const float*)d_in[11];
    const float* bn_s_v = (const float*)d_in[12];
    const float* w_c    = (const float*)d_in[13];
    const float* b_c    = (const float*)d_in[14];
    const float* bn_c_g = (const float*)d_in[15];
    const float* bn_c_b = (const float*)d_in[16];
    const float* bn_c_m = (const float*)d_in[17];
    const float* bn_c_v = (const float*)d_in[18];
    const float* w_fc   = (const float*)d_in[19];
    const float* b_fc   = (const float*)d_in[20];
    float* out = (float*)d_out;

    prep_kernel<<<1, 64>>>(b_t, bn_t_g, bn_t_b, bn_t_m, bn_t_v,
                           b_s, bn_s_g, bn_s_b, bn_s_m, bn_s_v,
                           b_c, bn_c_g, bn_c_b, bn_c_m, bn_c_v);

    dim3 g1((T1_ + 255) / 256, CH_, B_);      // (4, 22, 16)
    k1_temporal<<<g1, 128>>>(x, w_t);

    dim3 g2((T1_ + 127) / 128, B_);           // (8, 16)
    k2_spatial<<<g2, 128>>>(w_s);

    int nS = B_ * F_ * SLEN_;
    k2b_pool<<<(nS + 255) / 256, 256>>>();

    dim3 g3((U_ + 127) / 128, B_);            // (7, 16)
    k3_dconv<<<g3, 128>>>(w_c);

    dim3 g4(F_, B_);                          // (36, 16)
    k4_windows<<<g4, 1024>>>();

    k5_fc<<<B_, 128>>>(w_fc, b_fc, out);
}

// round 4
// speedup vs baseline: 2.1288x; 2.1288x over previous
#include <cuda_runtime.h>
#include <math.h>

#define B_     16
#define CH_    22
#define T_     1001
#define F_     36
#define KT_    65
#define T1_    937            // T - KT + 1
#define T1P_   944            // padded stride (16B multiple)
#define GC_    (F_*CH_)       // 792
#define KC_    15
#define U_     885            // E length
#define UP_    888            // padded stride
#define SLEN_  935            // S length
#define Q_     43
#define NCROPS_ 501
#define OUT_   4
#define FLAT_  (F_*Q_)        // 1548
#define EPSF   1e-5f

typedef unsigned long long ull;

// ---------------- scratch (device globals; no allocation) ----------------
__device__ float d_h1[(size_t)B_*GC_*T1P_];  // temporal act [b][f*CH+ch][t] (padded)
__device__ float d_h2[(size_t)B_*F_*T1P_];   // spatial act  [b][f][t] (padded)
__device__ float d_E [(size_t)B_*F_*UP_];    // elu(bn(D))   [b][f][u] (padded)
__device__ float d_G [(size_t)B_*FLAT_];     // summed pool2 [b][f*43+q]
__device__ float d_scale_t[F_], d_shift_t[F_];
__device__ float d_scale_s[F_], d_shift_s[F_];
__device__ float d_scale_c[F_], d_shift_c[F_];

// ---------------- f32x2 helpers ----------------
__device__ __forceinline__ ull pack2(float a, float b) {
    ull r;
    asm("mov.b64 %0, {%1, %2};" : "=l"(r) : "f"(a), "f"(b));
    return r;
}
__device__ __forceinline__ void fma2(ull& d, ull a, ull b) {
    asm("fma.rn.f32x2 %0, %1, %2, %0;" : "+l"(d) : "l"(a), "l"(b));
}
__device__ __forceinline__ float2 unpack2(ull v) {
    float2 r;
    asm("mov.b64 {%0, %1}, %2;" : "=f"(r.x), "=f"(r.y) : "l"(v));
    return r;
}
__device__ __forceinline__ float eluf(float x) {
    return x > 0.0f ? x : (__expf(x) - 1.0f);
}

// ---------------- prep: fold bias + BN ----------------
__global__ void prep_kernel(
    const float* __restrict__ b_t, const float* __restrict__ g_t, const float* __restrict__ bb_t,
    const float* __restrict__ m_t, const float* __restrict__ v_t,
    const float* __restrict__ b_s, const float* __restrict__ g_s, const float* __restrict__ bb_s,
    const float* __restrict__ m_s, const float* __restrict__ v_s,
    const float* __restrict__ b_c, const float* __restrict__ g_c, const float* __restrict__ bb_c,
    const float* __restrict__ m_c, const float* __restrict__ v_c)
{
    int i = threadIdx.x;
    if (i < F_) {
        float inv;
        inv = g_t[i] / sqrtf(v_t[i] + EPSF);
        d_scale_t[i] = inv; d_shift_t[i] = (b_t[i] - m_t[i]) * inv + bb_t[i];
        inv = g_s[i] / sqrtf(v_s[i] + EPSF);
        d_scale_s[i] = inv; d_shift_s[i] = (b_s[i] - m_s[i]) * inv + bb_s[i];
        inv = g_c[i] / sqrtf(v_c[i] + EPSF);
        d_scale_c[i] = inv; d_shift_c[i] = (b_c[i] - m_c[i]) * inv + bb_c[i];
    }
}

// ---------------- K1: temporal conv + BN + ELU ----------------
// grid (2*3, CH, B), block 128. Thread: 4 t x 12 f (6 f32x2 pairs).
__global__ void __launch_bounds__(128) k1_temporal(
    const float* __restrict__ x, const float* __restrict__ w_t)
{
    __shared__ float  sx[512 + 64];        // 576
    __shared__ float2 sw2[KT_][6];         // 65 x 6 f-pairs
    const int b   = blockIdx.z;
    const int ch  = blockIdx.y;
    const int tb  = blockIdx.x / 3;
    const int fg  = blockIdx.x % 3;
    const int f0  = fg * 12;
    const int t0  = tb * 512;
    const int tid = threadIdx.x;

    for (int i = tid; i < KT_ * 6; i += 128) {
        int k = i / 6, p = i % 6;
        sw2[k][p] = make_float2(w_t[(f0 + 2*p) * KT_ + k],
                                w_t[(f0 + 2*p + 1) * KT_ + k]);
    }
    const float* xp = x + ((size_t)b * CH_ + ch) * T_;
    for (int i = tid; i < 576; i += 128) {
        int tg = t0 + i;
        sx[i] = (tg < T_) ? xp[tg] : 0.0f;
    }
    __syncthreads();

    ull acc[4][6];
#pragma unroll
    for (int t = 0; t < 4; t++)
#pragma unroll
        for (int p = 0; p < 6; p++) acc[t][p] = 0ULL;

    const int tb4 = tid * 4;
#pragma unroll 13
    for (int k = 0; k < KT_; k++) {
        float x0 = sx[tb4 + k];
        float x1 = sx[tb4 + k + 1];
        float x2 = sx[tb4 + k + 2];
        float x3 = sx[tb4 + k + 3];
        ull xp0 = pack2(x0, x0), xp1 = pack2(x1, x1);
        ull xp2 = pack2(x2, x2), xp3 = pack2(x3, x3);
#pragma unroll
        for (int p = 0; p < 6; p++) {
            ull w = *(const ull*)&sw2[k][p];
            fma2(acc[0][p], xp0, w);
            fma2(acc[1][p], xp1, w);
            fma2(acc[2][p], xp2, w);
            fma2(acc[3][p], xp3, w);
        }
    }

    const int tbase = t0 + tb4;
    if (tbase < T1_) {
        float res[12][4];
#pragma unroll
        for (int p = 0; p < 6; p++) {
            float sc0 = d_scale_t[f0 + 2*p],     sh0 = d_shift_t[f0 + 2*p];
            float sc1 = d_scale_t[f0 + 2*p + 1], sh1 = d_shift_t[f0 + 2*p + 1];
#pragma unroll
            for (int t = 0; t < 4; t++) {
                float2 a = unpack2(acc[t][p]);
                res[2*p][t]     = eluf(fmaf(a.x, sc0, sh0));
                res[2*p + 1][t] = eluf(fmaf(a.y, sc1, sh1));
            }
        }
        const bool full = (tbase + 3 < T1_);
#pragma unroll
        for (int fl = 0; fl < 12; fl++) {
            int f = f0 + fl;
            float* row = d_h1 + ((size_t)b * GC_ + (size_t)f * CH_ + ch) * T1P_;
            if (full) {
                *(float4*)&row[tbase] = make_float4(res[fl][0], res[fl][1], res[fl][2], res[fl][3]);
            } else {
#pragma unroll
                for (int t = 0; t < 4; t++)
                    if (tbase + t < T1_) row[tbase + t] = res[fl][t];
            }
        }
    }
}

// ---------------- K2: spatial conv (36 x 792 GEMM) + BN + ELU ----------------
// grid (4, 6, B), block 128. Thread: 2 t x 6 f (3 f32x2 pairs). K-chunks of 24.
#define KCH_ 24
__global__ void __launch_bounds__(128) k2_spatial(const float* __restrict__ w_s)
{
    __shared__ float  sh[KCH_][256];       // 24.6 KB
    __shared__ float2 sw2[KCH_][3];
    const int b   = blockIdx.z;
    const int fg  = blockIdx.y;
    const int f0  = fg * 6;
    const int t0  = blockIdx.x * 256;
    const int tid = threadIdx.x;

    ull acc[2][3];
#pragma unroll
    for (int t = 0; t < 2; t++)
#pragma unroll
        for (int p = 0; p < 3; p++) acc[t][p] = 0ULL;

    for (int kk0 = 0; kk0 < GC_; kk0 += KCH_) {
        __syncthreads();
        // load 24 rows x 256 t (float4 coalesced)
        for (int i = tid; i < KCH_ * 64; i += 128) {
            int r = i >> 6, c = (i & 63) * 4;
            int tg = t0 + c;
            const float* row = d_h1 + ((size_t)b * GC_ + kk0 + r) * T1P_;
            float4 v;
            if (tg + 3 < T1_) {
                v = *(const float4*)&row[tg];
            } else {
                v.x = (tg     < T1_) ? row[tg]     : 0.0f;
                v.y = (tg + 1 < T1_) ? row[tg + 1] : 0.0f;
                v.z = (tg + 2 < T1_) ? row[tg + 2] : 0.0f;
                v.w = 0.0f;
            }
            *(float4*)&sh[r][c] = v;
        }
        for (int i = tid; i < KCH_ * 3; i += 128) {
            int r = i / 3, p = i % 3;
            sw2[r][p] = make_float2(w_s[(size_t)(f0 + 2*p) * GC_ + kk0 + r],
                                    w_s[(size_t)(f0 + 2*p + 1) * GC_ + kk0 + r]);
        }
        __syncthreads();
#pragma unroll
        for (int r = 0; r < KCH_; r++) {
            float2 hv = *(const float2*)&sh[r][tid * 2];
            ull h0 = pack2(hv.x, hv.x);
            ull h1 = pack2(hv.y, hv.y);
#pragma unroll
            for (int p = 0; p < 3; p++) {
                ull w = *(const ull*)&sw2[r][p];
                fma2(acc[0][p], h0, w);
                fma2(acc[1][p], h1, w);
            }
        }
    }

    const int t = t0 + tid * 2;
    if (t < T1_) {
        bool both = (t + 1 < T1_);
#pragma unroll
        for (int p = 0; p < 3; p++) {
            float sc0 = d_scale_s[f0 + 2*p],     sh0 = d_shift_s[f0 + 2*p];
            float sc1 = d_scale_s[f0 + 2*p + 1], sh1 = d_shift_s[f0 + 2*p + 1];
            float2 a0 = unpack2(acc[0][p]);   // t
            float2 a1 = unpack2(acc[1][p]);   // t+1
            float v00 = eluf(fmaf(a0.x, sc0, sh0)), v01 = eluf(fmaf(a1.x, sc0, sh0));
            float v10 = eluf(fmaf(a0.y, sc1, sh1)), v11 = eluf(fmaf(a1.y, sc1, sh1));
            float* r0 = d_h2 + ((size_t)b * F_ + f0 + 2*p) * T1P_;
            float* r1 = d_h2 + ((size_t)b * F_ + f0 + 2*p + 1) * T1P_;
            if (both) {
                *(float2*)&r0[t] = make_float2(v00, v01);
                *(float2*)&r1[t] = make_float2(v10, v11);
            } else {
                r0[t] = v00; r1[t] = v10;
            }
        }
    }
}

// ---------------- K3: 3-mean + dilation-3 conv + BN + ELU -> E ----------------
// grid (4, 6, B), block 128. Thread: 2 u x 6 f. g-chunks of 6 (3-mean fused in loader).
__global__ void __launch_bounds__(128) k3_dconv(const float* __restrict__ w_c)
{
    __shared__ float  sS[6][304];          // 298 S values per g (+pad)
    __shared__ float2 sw2[6][KC_][3];
    const int b   = blockIdx.z;
    const int fg  = blockIdx.y;
    const int f0  = fg * 6;
    const int u0  = blockIdx.x * 256;
    const int tid = threadIdx.x;

    ull acc[2][3];
#pragma unroll
    for (int t = 0; t < 2; t++)
#pragma unroll
        for (int p = 0; p < 3; p++) acc[t][p] = 0ULL;

    const int uu = tid * 2;
    for (int g0 = 0; g0 < F_; g0 += 6) {
        __syncthreads();
        for (int i = tid; i < 6 * 298; i += 128) {
            int g = i / 298, k = i % 298;
            int t = u0 + k;
            float s = 0.0f;
            if (t < SLEN_) {
                const float* row = d_h2 + ((size_t)b * F_ + g0 + g) * T1P_;
                s = (row[t] + row[t + 1] + row[t + 2]) * (1.0f / 3.0f);
            }
            sS[g][k] = s;
        }
        for (int i = tid; i < 6 * KC_ * 3; i += 128) {
            int g = i / (KC_ * 3), r = i % (KC_ * 3), j = r / 3, p = r % 3;
            sw2[g][j][p] = make_float2(
                w_c[((size_t)(f0 + 2*p)     * F_ + g0 + g) * KC_ + j],
                w_c[((size_t)(f0 + 2*p + 1) * F_ + g0 + g) * KC_ + j]);
        }
        __syncthreads();
#pragma unroll
        for (int g = 0; g < 6; g++) {
#pragma unroll
            for (int j = 0; j < KC_; j++) {
                float s0 = sS[g][uu + 3*j];
                float s1 = sS[g][uu + 1 + 3*j];
                ull p0 = pack2(s0, s0);
                ull p1 = pack2(s1, s1);
#pragma unroll
                for (int p = 0; p < 3; p++) {
                    ull w = *(const ull*)&sw2[g][j][p];
                    fma2(acc[0][p], p0, w);
                    fma2(acc[1][p], p1, w);
                }
            }
        }
    }

    const int u = u0 + uu;
    if (u < U_) {
        bool both = (u + 1 < U_);
#pragma unroll
        for (int p = 0; p < 3; p++) {
            float sc0 = d_scale_c[f0 + 2*p],     sh0 = d_shift_c[f0 + 2*p];
            float sc1 = d_scale_c[f0 + 2*p + 1], sh1 = d_shift_c[f0 + 2*p + 1];
            float2 a0 = unpack2(acc[0][p]);   // u
            float2 a1 = unpack2(acc[1][p]);   // u+1
            float v00 = eluf(fmaf(a0.x, sc0, sh0)), v01 = eluf(fmaf(a1.x, sc0, sh0));
            float v10 = eluf(fmaf(a0.y, sc1, sh1)), v11 = eluf(fmaf(a1.y, sc1, sh1));
            float* r0 = d_E + ((size_t)b * F_ + f0 + 2*p) * UP_;
            float* r1 = d_E + ((size_t)b * F_ + f0 + 2*p + 1) * UP_;
            if (both) {
                *(float2*)&r0[u] = make_float2(v00, v01);
                *(float2*)&r1[u] = make_float2(v10, v11);
            } else {
                r0[u] = v00; r1[u] = v10;
            }
        }
    }
}

// ---------------- K4: per-(b,f) prefix scan + windowed sums -> G ----------------
__global__ void __launch_bounds__(1024) k4_windows(void)
{
    __shared__ float buf0[1024];
    __shared__ float buf1[1024];
    const int b = blockIdx.y, f = blockIdx.x;
    const int tid = threadIdx.x;
    const float* Ep = d_E + ((size_t)b * F_ + f) * UP_;

    buf0[tid] = (tid < U_) ? Ep[tid] : 0.0f;
    __syncthreads();

    float* src = buf0;
    float* dst = buf1;
#pragma unroll
    for (int off = 1; off < 1024; off <<= 1) {
        dst[tid] = src[tid] + ((tid >= off) ? src[tid - off] : 0.0f);
        __syncthreads();
        float* tmp = src; src = dst; dst = tmp;
    }

    if (tid < Q_) {
        int q = tid;
        float s = 0.0f;
#pragma unroll
        for (int c = 0; c <= 6; c += 3) {
            int a = 9 * q + c;
            float lo = (a > 0) ? src[a - 1] : 0.0f;
            s += src[a + 500] - lo;
        }
        d_G[(size_t)b * FLAT_ + f * Q_ + q] = s * (1.0f / 3.0f);
    }
}

// ---------------- K5: FC reduce ----------------
__global__ void __launch_bounds__(128) k5_fc(
    const float* __restrict__ w_fc, const float* __restrict__ b_fc,
    float* __restrict__ out)
{
    __shared__ float red[OUT_][128];
    const int b = blockIdx.x;
    const int tid = threadIdx.x;

    float p[OUT_];
#pragma unroll
    for (int o = 0; o < OUT_; o++) p[o] = 0.0f;

    for (int i = tid; i < FLAT_; i += 128) {
        float g = d_G[(size_t)b * FLAT_ + i];
#pragma unroll
        for (int o = 0; o < OUT_; o++)
            p[o] = fmaf(g, w_fc[(size_t)o * FLAT_ + i], p[o]);
    }
#pragma unroll
    for (int o = 0; o < OUT_; o++) red[o][tid] = p[o];
    __syncthreads();
    for (int s = 64; s > 0; s >>= 1) {
        if (tid < s) {
#pragma unroll
            for (int o = 0; o < OUT_; o++) red[o][tid] += red[o][tid + s];
        }
        __syncthreads();
    }
    if (tid < OUT_)
        out[b * OUT_ + tid] = red[tid][0] * (1.0f / NCROPS_) + b_fc[tid];
}

// ---------------- launch ----------------
extern "C" void kernel_launch(void* const* d_in, const int* in_sizes, int n_in,
                              void* d_out, int out_size)
{
    const float* x      = (const float*)d_in[0];
    const float* w_t    = (const float*)d_in[1];
    const float* b_t    = (const float*)d_in[2];
    const float* bn_t_g = (const float*)d_in[3];
    const float* bn_t_b = (const float*)d_in[4];
    const float* bn_t_m = (const float*)d_in[5];
    const float* bn_t_v = (const float*)d_in[6];
    const float* w_s    = (const float*)d_in[7];
    const float* b_s    = (const float*)d_in[8];
    const float* bn_s_g = (const float*)d_in[9];
    const float* bn_s_b = (const float*)d_in[10];
    const float* bn_s_m = (const float*)d_in[11];
    const float* bn_s_v = (const float*)d_in[12];
    const float* w_c    = (const float*)d_in[13];
    const float* b_c    = (const float*)d_in[14];
    const float* bn_c_g = (const float*)d_in[15];
    const float* bn_c_b = (const float*)d_in[16];
    const float* bn_c_m = (const float*)d_in[17];
    const float* bn_c_v = (const float*)d_in[18];
    const float* w_fc   = (const float*)d_in[19];
    const float* b_fc   = (const float*)d_in[20];
    float* out = (float*)d_out;

    prep_kernel<<<1, 64>>>(b_t, bn_t_g, bn_t_b, bn_t_m, bn_t_v,
                           b_s, bn_s_g, bn_s_b, bn_s_m, bn_s_v,
                           b_c, bn_c_g, bn_c_b, bn_c_m, bn_c_v);

    dim3 g1(6, CH_, B_);                      // (2 t-tiles x 3 f-groups, 22, 16)
    k1_temporal<<<g1, 128>>>(x, w_t);

    dim3 g2(4, 6, B_);                        // (t-tiles, f-groups, b)
    k2_spatial<<<g2, 128>>>(w_s);

    dim3 g3(4, 6, B_);
    k3_dconv<<<g3, 128>>>(w_c);

    dim3 g4(F_, B_);
    k4_windows<<<g4, 1024>>>();

    k5_fc<<<B_, 128>>>(w_fc, b_fc, out);
}

// round 5
// speedup vs baseline: 4.3966x; 2.0653x over previous
#include <cuda_runtime.h>
#include <math.h>

#define B_     16
#define CH_    22
#define T_     1001
#define F_     36
#define KT_    65
#define T1_    937            // T - KT + 1
#define T1P_   944            // padded stride
#define GC_    (F_*CH_)       // 792
#define KC_    15
#define U_     885            // E length
#define UP_    888            // padded stride
#define SLEN_  935            // S length
#define SP_    944            // S padded stride
#define Q_     43
#define NCROPS_ 501
#define OUT_   4
#define FLAT_  (F_*Q_)        // 1548
#define EPSF   1e-5f

#define KSPLIT2_ 4
#define KCHUNK2_ (GC_/KSPLIT2_)   // 198
#define GSPLIT3_ 3
#define GCHUNK3_ (F_/GSPLIT3_)    // 12

typedef unsigned long long ull;

// ---------------- scratch (device globals; no allocation) ----------------
__device__ float d_h1[(size_t)B_*GC_*T1P_ + 1024]; // temporal act [b][f*CH+ch][t] (+OOB pad)
__device__ float d_p2[(size_t)KSPLIT2_*B_*F_*T1P_]; // k2 partials [s][b][f][t]
__device__ float d_S [(size_t)B_*F_*SP_];           // 3-mean of elu(bn(spatial)) [b][f][t]
__device__ float d_p3[(size_t)GSPLIT3_*B_*F_*UP_];  // k3 partials [gs][b][f][u]
__device__ float d_G [(size_t)B_*FLAT_];            // summed pool2 [b][f*43+q]
__device__ float d_scale_t[F_], d_shift_t[F_];
__device__ float d_scale_s[F_], d_shift_s[F_];
__device__ float d_scale_c[F_], d_shift_c[F_];

// ---------------- f32x2 helpers ----------------
__device__ __forceinline__ ull pack2(float a, float b) {
    ull r;
    asm("mov.b64 %0, {%1, %2};" : "=l"(r) : "f"(a), "f"(b));
    return r;
}
__device__ __forceinline__ void fma2(ull& d, ull a, ull b) {
    asm("fma.rn.f32x2 %0, %1, %2, %0;" : "+l"(d) : "l"(a), "l"(b));
}
__device__ __forceinline__ float2 unpack2(ull v) {
    float2 r;
    asm("mov.b64 {%0, %1}, %2;" : "=f"(r.x), "=f"(r.y) : "l"(v));
    return r;
}
__device__ __forceinline__ float eluf(float x) {
    return x > 0.0f ? x : (__expf(x) - 1.0f);
}

// ---------------- prep: fold bias + BN ----------------
__global__ void prep_kernel(
    const float* __restrict__ b_t, const float* __restrict__ g_t, const float* __restrict__ bb_t,
    const float* __restrict__ m_t, const float* __restrict__ v_t,
    const float* __restrict__ b_s, const float* __restrict__ g_s, const float* __restrict__ bb_s,
    const float* __restrict__ m_s, const float* __restrict__ v_s,
    const float* __restrict__ b_c, const float* __restrict__ g_c, const float* __restrict__ bb_c,
    const float* __restrict__ m_c, const float* __restrict__ v_c)
{
    int i = threadIdx.x;
    if (i < F_) {
        float inv;
        inv = g_t[i] / sqrtf(v_t[i] + EPSF);
        d_scale_t[i] = inv; d_shift_t[i] = (b_t[i] - m_t[i]) * inv + bb_t[i];
        inv = g_s[i] / sqrtf(v_s[i] + EPSF);
        d_scale_s[i] = inv; d_shift_s[i] = (b_s[i] - m_s[i]) * inv + bb_s[i];
        inv = g_c[i] / sqrtf(v_c[i] + EPSF);
        d_scale_c[i] = inv; d_shift_c[i] = (b_c[i] - m_c[i]) * inv + bb_c[i];
    }
}

// ---------------- K1: temporal conv + BN + ELU ----------------
// grid (2*3, CH, B), block 128. Thread: 4 t x 12 f (6 f32x2 pairs).
__global__ void __launch_bounds__(128) k1_temporal(
    const float* __restrict__ x, const float* __restrict__ w_t)
{
    __shared__ float sx[512 + 64];         // 576
    __shared__ ull   sw[KT_][6];           // f32x2 weight pairs, 48B rows (16B aligned)
    const int b   = blockIdx.z;
    const int ch  = blockIdx.y;
    const int tb  = blockIdx.x / 3;
    const int fg  = blockIdx.x % 3;
    const int f0  = fg * 12;
    const int t0  = tb * 512;
    const int tid = threadIdx.x;

    for (int i = tid; i < KT_ * 6; i += 128) {
        int k = i / 6, p = i % 6;
        sw[k][p] = pack2(w_t[(f0 + 2*p) * KT_ + k],
                         w_t[(f0 + 2*p + 1) * KT_ + k]);
    }
    const float* xp = x + ((size_t)b * CH_ + ch) * T_;
    for (int i = tid; i < 576; i += 128) {
        int tg = t0 + i;
        sx[i] = (tg < T_) ? xp[tg] : 0.0f;
    }
    __syncthreads();

    ull acc[4][6];
#pragma unroll
    for (int t = 0; t < 4; t++)
#pragma unroll
        for (int p = 0; p < 6; p++) acc[t][p] = 0ULL;

    const int tb4 = tid * 4;
#pragma unroll 5
    for (int k = 0; k < KT_; k++) {
        float x0 = sx[tb4 + k];
        float x1 = sx[tb4 + k + 1];
        float x2 = sx[tb4 + k + 2];
        float x3 = sx[tb4 + k + 3];
        ull xp0 = pack2(x0, x0), xp1 = pack2(x1, x1);
        ull xp2 = pack2(x2, x2), xp3 = pack2(x3, x3);
        ulonglong2 w01 = *(const ulonglong2*)&sw[k][0];
        ulonglong2 w23 = *(const ulonglong2*)&sw[k][2];
        ulonglong2 w45 = *(const ulonglong2*)&sw[k][4];
        ull wv[6] = {w01.x, w01.y, w23.x, w23.y, w45.x, w45.y};
#pragma unroll
        for (int p = 0; p < 6; p++) {
            fma2(acc[0][p], xp0, wv[p]);
            fma2(acc[1][p], xp1, wv[p]);
            fma2(acc[2][p], xp2, wv[p]);
            fma2(acc[3][p], xp3, wv[p]);
        }
    }

    const int tbase = t0 + tb4;
    if (tbase < T1_) {
        float res[12][4];
#pragma unroll
        for (int p = 0; p < 6; p++) {
            float sc0 = d_scale_t[f0 + 2*p],     sh0 = d_shift_t[f0 + 2*p];
            float sc1 = d_scale_t[f0 + 2*p + 1], sh1 = d_shift_t[f0 + 2*p + 1];
#pragma unroll
            for (int t = 0; t < 4; t++) {
                float2 a = unpack2(acc[t][p]);
                res[2*p][t]     = eluf(fmaf(a.x, sc0, sh0));
                res[2*p + 1][t] = eluf(fmaf(a.y, sc1, sh1));
            }
        }
        const bool full = (tbase + 3 < T1_);
#pragma unroll
        for (int fl = 0; fl < 12; fl++) {
            int f = f0 + fl;
            float* row = d_h1 + ((size_t)b * GC_ + (size_t)f * CH_ + ch) * T1P_;
            if (full) {
                *(float4*)&row[tbase] = make_float4(res[fl][0], res[fl][1], res[fl][2], res[fl][3]);
            } else {
#pragma unroll
                for (int t = 0; t < 4; t++)
                    if (tbase + t < T1_) row[tbase + t] = res[fl][t];
            }
        }
    }
}

// ---------------- K2: spatial conv, split-K partials ----------------
// grid (8 t-tiles, 2 f-groups, B*4 splits), block 128. Thread: 1 t x 18 f (9 pairs).
// No inner barriers: weights resident in smem, h1 streamed from L2 via LDG.
__global__ void __launch_bounds__(128) k2_spatial(const float* __restrict__ w_s)
{
    __shared__ ull sw[KCHUNK2_][10];       // 9 used + pad (80B rows, 16B aligned)
    const int b   = blockIdx.z >> 2;
    const int s   = blockIdx.z & 3;
    const int f0  = blockIdx.y * 18;
    const int t0  = blockIdx.x * 128;
    const int tid = threadIdx.x;
    const int ks0 = s * KCHUNK2_;

    for (int i = tid; i < KCHUNK2_ * 9; i += 128) {
        int k = i / 9, p = i % 9;
        sw[k][p] = pack2(w_s[(size_t)(f0 + 2*p) * GC_ + ks0 + k],
                         w_s[(size_t)(f0 + 2*p + 1) * GC_ + ks0 + k]);
    }
    __syncthreads();

    const int t = t0 + tid;
    const float* hbase = d_h1 + ((size_t)(b * GC_ + ks0)) * T1P_ + t;

    ull acc[9];
#pragma unroll
    for (int p = 0; p < 9; p++) acc[p] = 0ULL;

#pragma unroll 1
    for (int kk = 0; kk < KCHUNK2_; kk += 6) {
        float hv[6];
#pragma unroll
        for (int j = 0; j < 6; j++)
            hv[j] = hbase[(size_t)(kk + j) * T1P_];   // may read pad garbage; masked at store
#pragma unroll
        for (int j = 0; j < 6; j++) {
            ull hp = pack2(hv[j], hv[j]);
            const ull* wr = &sw[kk + j][0];
            ulonglong2 w01 = *(const ulonglong2*)(wr);
            ulonglong2 w23 = *(const ulonglong2*)(wr + 2);
            ulonglong2 w45 = *(const ulonglong2*)(wr + 4);
            ulonglong2 w67 = *(const ulonglong2*)(wr + 6);
            ull w8 = wr[8];
            fma2(acc[0], hp, w01.x); fma2(acc[1], hp, w01.y);
            fma2(acc[2], hp, w23.x); fma2(acc[3], hp, w23.y);
            fma2(acc[4], hp, w45.x); fma2(acc[5], hp, w45.y);
            fma2(acc[6], hp, w67.x); fma2(acc[7], hp, w67.y);
            fma2(acc[8], hp, w8);
        }
    }

    if (t < T1_) {
        float* pb = d_p2 + ((size_t)s * B_ * F_ + (size_t)b * F_) * T1P_;
#pragma unroll
        for (int p = 0; p < 9; p++) {
            float2 a = unpack2(acc[p]);
            pb[(size_t)(f0 + 2*p) * T1P_ + t]     = a.x;
            pb[(size_t)(f0 + 2*p + 1) * T1P_ + t] = a.y;
        }
    }
}

// ---------------- K2e: reduce partials + BN + ELU + 3-mean -> S ----------------
// grid (F, B), block 256.
__global__ void __launch_bounds__(256) k2e_reduce(void)
{
    __shared__ float e[T1P_];
    const int b = blockIdx.y, f = blockIdx.x;
    const int tid = threadIdx.x;
    const size_t row = ((size_t)b * F_ + f) * T1P_;
    const float sc = d_scale_s[f], sh = d_shift_s[f];
    const size_t pstride = (size_t)B_ * F_ * T1P_;

    for (int t = tid; t < T1_; t += 256) {
        float v = d_p2[row + t] + d_p2[pstride + row + t]
                + d_p2[2 * pstride + row + t] + d_p2[3 * pstride + row + t];
        e[t] = eluf(fmaf(v, sc, sh));
    }
    __syncthreads();

    float* Sp = d_S + ((size_t)b * F_ + f) * SP_;
    for (int t = tid; t < SLEN_; t += 256)
        Sp[t] = (e[t] + e[t + 1] + e[t + 2]) * (1.0f / 3.0f);
}

// ---------------- K3: dilation-3 conv, split-g partials ----------------
// grid (7 u-tiles, 3 f-groups, B*3 g-splits), block 128. Thread: 1 u x 12 f (6 pairs).
__global__ void __launch_bounds__(128) k3_dconv(const float* __restrict__ w_c)
{
    __shared__ float sS[GCHUNK3_][176];             // 170 used
    __shared__ ull   sw[GCHUNK3_ * KC_][6];         // 48B rows
    const int b   = blockIdx.z / 3;
    const int gs  = blockIdx.z % 3;
    const int f0  = blockIdx.y * 12;
    const int g0  = gs * GCHUNK3_;
    const int u0  = blockIdx.x * 128;
    const int tid = threadIdx.x;

    for (int i = tid; i < GCHUNK3_ * 170; i += 128) {
        int g = i / 170, k = i % 170;
        int t = u0 + k;
        sS[g][k] = (t < SLEN_) ? d_S[((size_t)b * F_ + g0 + g) * SP_ + t] : 0.0f;
    }
    for (int i = tid; i < GCHUNK3_ * KC_ * 6; i += 128) {
        int idx = i / 6, p = i % 6;
        int g = idx / KC_, j = idx % KC_;
        sw[idx][p] = pack2(w_c[((size_t)(f0 + 2*p) * F_ + g0 + g) * KC_ + j],
                           w_c[((size_t)(f0 + 2*p + 1) * F_ + g0 + g) * KC_ + j]);
    }
    __syncthreads();

    ull acc[6];
#pragma unroll
    for (int p = 0; p < 6; p++) acc[p] = 0ULL;

#pragma unroll 1
    for (int g = 0; g < GCHUNK3_; g++) {
#pragma unroll
        for (int j = 0; j < KC_; j++) {
            float s = sS[g][tid + 3*j];
            ull sp = pack2(s, s);
            const ull* wr = &sw[g * KC_ + j][0];
            ulonglong2 w01 = *(const ulonglong2*)(wr);
            ulonglong2 w23 = *(const ulonglong2*)(wr + 2);
            ulonglong2 w45 = *(const ulonglong2*)(wr + 4);
            fma2(acc[0], sp, w01.x); fma2(acc[1], sp, w01.y);
            fma2(acc[2], sp, w23.x); fma2(acc[3], sp, w23.y);
            fma2(acc[4], sp, w45.x); fma2(acc[5], sp, w45.y);
        }
    }

    const int u = u0 + tid;
    if (u < U_) {
        float* pb = d_p3 + ((size_t)gs * B_ * F_ + (size_t)b * F_) * UP_;
#pragma unroll
        for (int p = 0; p < 6; p++) {
            float2 a = unpack2(acc[p]);
            pb[(size_t)(f0 + 2*p) * UP_ + u]     = a.x;
            pb[(size_t)(f0 + 2*p + 1) * UP_ + u] = a.y;
        }
    }
}

// ---------------- K4: reduce partials + BN + ELU + prefix scan + windows -> G ----------------
// grid (F, B), block 1024. Warp-shuffle 3-phase scan.
__global__ void __launch_bounds__(1024) k4_windows(void)
{
    __shared__ float wsum[32];
    __shared__ float ps[1025];
    const int b = blockIdx.y, f = blockIdx.x;
    const int tid = threadIdx.x;
    const int lane = tid & 31, wid = tid >> 5;
    const size_t row = ((size_t)b * F_ + f) * UP_;
    const size_t pstride = (size_t)B_ * F_ * UP_;

    float e = 0.0f;
    if (tid < U_) {
        float v = d_p3[row + tid] + d_p3[pstride + row + tid] + d_p3[2 * pstride + row + tid];
        e = eluf(fmaf(v, d_scale_c[f], d_shift_c[f]));
    }

    float xv = e;
#pragma unroll
    for (int off = 1; off < 32; off <<= 1) {
        float y = __shfl_up_sync(0xffffffffu, xv, off);
        if (lane >= off) xv += y;
    }
    if (lane == 31) wsum[wid] = xv;
    __syncthreads();
    if (wid == 0) {
        float sv = wsum[lane];
#pragma unroll
        for (int off = 1; off < 32; off <<= 1) {
            float y = __shfl_up_sync(0xffffffffu, sv, off);
            if (lane >= off) sv += y;
        }
        wsum[lane] = sv;
    }
    __syncthreads();
    float base = (wid > 0) ? wsum[wid - 1] : 0.0f;
    ps[tid + 1] = xv + base;
    if (tid == 0) ps[0] = 0.0f;
    __syncthreads();

    if (tid < Q_) {
        int q = tid;
        float s = 0.0f;
#pragma unroll
        for (int c = 0; c <= 6; c += 3)
            s += ps[9 * q + c + 501] - ps[9 * q + c];
        d_G[(size_t)b * FLAT_ + f * Q_ + q] = s * (1.0f / 3.0f);
    }
}

// ---------------- K5: FC reduce ----------------
__global__ void __launch_bounds__(128) k5_fc(
    const float* __restrict__ w_fc, const float* __restrict__ b_fc,
    float* __restrict__ out)
{
    __shared__ float red[OUT_][128];
    const int b = blockIdx.x;
    const int tid = threadIdx.x;

    float p[OUT_];
#pragma unroll
    for (int o = 0; o < OUT_; o++) p[o] = 0.0f;

    for (int i = tid; i < FLAT_; i += 128) {
        float g = d_G[(size_t)b * FLAT_ + i];
#pragma unroll
        for (int o = 0; o < OUT_; o++)
            p[o] = fmaf(g, w_fc[(size_t)o * FLAT_ + i], p[o]);
    }
#pragma unroll
    for (int o = 0; o < OUT_; o++) red[o][tid] = p[o];
    __syncthreads();
    for (int s = 64; s > 0; s >>= 1) {
        if (tid < s) {
#pragma unroll
            for (int o = 0; o < OUT_; o++) red[o][tid] += red[o][tid + s];
        }
        __syncthreads();
    }
    if (tid < OUT_)
        out[b * OUT_ + tid] = red[tid][0] * (1.0f / NCROPS_) + b_fc[tid];
}

// ---------------- launch ----------------
extern "C" void kernel_launch(void* const* d_in, const int* in_sizes, int n_in,
                              void* d_out, int out_size)
{
    const float* x      = (const float*)d_in[0];
    const float* w_t    = (const float*)d_in[1];
    const float* b_t    = (const float*)d_in[2];
    const float* bn_t_g = (const float*)d_in[3];
    const float* bn_t_b = (const float*)d_in[4];
    const float* bn_t_m = (const float*)d_in[5];
    const float* bn_t_v = (const float*)d_in[6];
    const float* w_s    = (const float*)d_in[7];
    const float* b_s    = (const float*)d_in[8];
    const float* bn_s_g = (const float*)d_in[9];
    const float* bn_s_b = (const float*)d_in[10];
    const float* bn_s_m = (const float*)d_in[11];
    const float* bn_s_v = (const float*)d_in[12];
    const float* w_c    = (const float*)d_in[13];
    const float* b_c    = (const float*)d_in[14];
    const float* bn_c_g = (const float*)d_in[15];
    const float* bn_c_b = (const float*)d_in[16];
    const float* bn_c_m = (const float*)d_in[17];
    const float* bn_c_v = (const float*)d_in[18];
    const float* w_fc   = (const float*)d_in[19];
    const float* b_fc   = (const float*)d_in[20];
    float* out = (float*)d_out;

    prep_kernel<<<1, 64>>>(b_t, bn_t_g, bn_t_b, bn_t_m, bn_t_v,
                           b_s, bn_s_g, bn_s_b, bn_s_m, bn_s_v,
                           b_c, bn_c_g, bn_c_b, bn_c_m, bn_c_v);

    dim3 g1(6, CH_, B_);                      // 2112 blocks
    k1_temporal<<<g1, 128>>>(x, w_t);

    dim3 g2(8, 2, B_ * KSPLIT2_);             // 1024 blocks
    k2_spatial<<<g2, 128>>>(w_s);

    dim3 g2e(F_, B_);                         // 576 blocks
    k2e_reduce<<<g2e, 256>>>();

    dim3 g3(7, 3, B_ * GSPLIT3_);             // 1008 blocks
    k3_dconv<<<g3, 128>>>(w_c);

    dim3 g4(F_, B_);                          // 576 blocks
    k4_windows<<<g4, 1024>>>();

    k5_fc<<<B_, 128>>>(w_fc, b_fc, out);
}